// round 17
// baseline (speedup 1.0000x reference)
#include <cuda_runtime.h>
#include <cstdint>

#define N_NODES 50000
#define N_EDGES 800000
#define IN_DIM  128
#define OUT_DIM 128
#define EDGE_DIM 64

#define ETILE      64                    // edges per tile
#define NTILES_TOT 12500                 // 800000 / 64
#define EGRID      444                   // 148 SMs * occ 3 -> single wave

// dynamic smem layout (floats)
#define SMF_W      0                     // Wsh[64][132] = 8448 floats
#define SMF_E      8448                  // Esh[2][32][68] = 4352 floats
#define SM_TOTAL_B ((8448 + 4352) * 4)   // 51200 bytes

typedef unsigned long long u64;

// Scratch for node projections (allocation-free per harness rules).
__device__ __align__(16) float g_HU[(size_t)N_NODES * OUT_DIM];
__device__ __align__(16) float g_HW[(size_t)N_NODES * OUT_DIM];
__device__ int g_idx_is64;

__device__ __forceinline__ u64 pack2(float lo, float hi) {
    u64 r; asm("mov.b64 %0, {%1, %2};" : "=l"(r) : "f"(lo), "f"(hi)); return r;
}
__device__ __forceinline__ void fma2(u64& d, u64 a, u64 b) {
    asm("fma.rn.f32x2 %0, %1, %2, %3;" : "=l"(d) : "l"(a), "l"(b), "l"(d));
}
__device__ __forceinline__ float2 unpack2(u64 v) {
    float2 f; asm("mov.b64 {%0, %1}, %2;" : "=f"(f.x), "=f"(f.y) : "l"(v)); return f;
}
__device__ __forceinline__ int clamp_idx(int v) {
    return v < 0 ? 0 : (v >= N_NODES ? N_NODES - 1 : v);
}
__device__ __forceinline__ int fetch_idx(const int* __restrict__ ei32,
                                         int is64, size_t pos) {
    int v = is64 ? ei32[2 * pos] : ei32[pos];
    return clamp_idx(v);
}

// ---------------------------------------------------------------------------
// Node projection (both W_hu and W_hw via blockIdx.y) — proven kernel.
// Block (0,0) also performs index-dtype detection (edge launches after).
// ---------------------------------------------------------------------------
__global__ __launch_bounds__(256, 2)
void node_proj_kernel(const float* __restrict__ h,
                      const float* __restrict__ Whu,
                      const float* __restrict__ Whw,
                      const int* __restrict__ ei32)
{
    __shared__ __align__(16) float Wsh[32][132];
    __shared__ __align__(16) float Hsh[32][132];

    if (blockIdx.x == 0 && blockIdx.y == 0 && threadIdx.x == 0) {
        int all_zero = 1;
        for (int i = 0; i < 256; ++i)
            if (ei32[2 * i + 1] != 0) { all_zero = 0; break; }
        g_idx_is64 = all_zero;
    }

    const float* __restrict__ W   = blockIdx.y ? Whw : Whu;
    float*       __restrict__ dst = blockIdx.y ? g_HW : g_HU;

    const int tid = threadIdx.x;
    const int tx  = tid & 31;
    const int ty  = tid >> 5;
    const int n0  = blockIdx.x * 128;

    u64 acc[8][4];
#pragma unroll
    for (int p = 0; p < 8; ++p)
#pragma unroll
        for (int j = 0; j < 4; ++j) acc[p][j] = 0ULL;

#pragma unroll 1
    for (int s = 0; s < 4; ++s) {
        __syncthreads();
#pragma unroll
        for (int it = 0; it < 4; ++it) {
            int idx = it * 256 + tid;
            int o   = idx >> 3;
            int kq  = idx & 7;
            float4 w = *reinterpret_cast<const float4*>(W + (size_t)o * IN_DIM + s * 32 + kq * 4);
            Wsh[kq * 4 + 0][o] = w.x; Wsh[kq * 4 + 1][o] = w.y;
            Wsh[kq * 4 + 2][o] = w.z; Wsh[kq * 4 + 3][o] = w.w;
        }
#pragma unroll
        for (int it = 0; it < 4; ++it) {
            int idx = it * 256 + tid;
            int ln  = idx >> 3;
            int kq  = idx & 7;
            int n   = n0 + ln;
            float4 v = make_float4(0.f, 0.f, 0.f, 0.f);
            if (n < N_NODES)
                v = *reinterpret_cast<const float4*>(h + (size_t)n * IN_DIM + s * 32 + kq * 4);
            Hsh[kq * 4 + 0][ln] = v.x; Hsh[kq * 4 + 1][ln] = v.y;
            Hsh[kq * 4 + 2][ln] = v.z; Hsh[kq * 4 + 3][ln] = v.w;
        }
        __syncthreads();

#pragma unroll
        for (int k = 0; k < 32; ++k) {
            float4 w = *reinterpret_cast<const float4*>(&Wsh[k][tx * 4]);
            u64 w2[4];
            w2[0] = pack2(w.x, w.x); w2[1] = pack2(w.y, w.y);
            w2[2] = pack2(w.z, w.z); w2[3] = pack2(w.w, w.w);
            u64 ev[8];
#pragma unroll
            for (int q = 0; q < 4; ++q) {
                ulonglong2 ep = *reinterpret_cast<const ulonglong2*>(&Hsh[k][ty * 16 + q * 4]);
                ev[2 * q] = ep.x; ev[2 * q + 1] = ep.y;
            }
#pragma unroll
            for (int p = 0; p < 8; ++p)
#pragma unroll
                for (int j = 0; j < 4; ++j)
                    fma2(acc[p][j], ev[p], w2[j]);
        }
    }

#pragma unroll
    for (int p = 0; p < 8; ++p) {
        int na = n0 + ty * 16 + 2 * p;
        float2 v0 = unpack2(acc[p][0]), v1 = unpack2(acc[p][1]);
        float2 v2 = unpack2(acc[p][2]), v3 = unpack2(acc[p][3]);
        if (na < N_NODES)
            *reinterpret_cast<float4*>(dst + (size_t)na * OUT_DIM + tx * 4) =
                make_float4(v0.x, v1.x, v2.x, v3.x);
        if (na + 1 < N_NODES)
            *reinterpret_cast<float4*>(dst + (size_t)(na + 1) * OUT_DIM + tx * 4) =
                make_float4(v0.y, v1.y, v2.y, v3.y);
    }
}

// ---------------------------------------------------------------------------
// Fused edge kernel v12: R16 structure (distinct-byte mapping, 32-k stages,
// deferred epilogue) + BATCHED-MLP epilogue: per half (2 edge-pairs), load
// 4+4 indices then issue all 8 row-gather LDG.128s before any arithmetic.
// One ~600cyc L2 exposure per half instead of four per tile.
// ---------------------------------------------------------------------------
__global__ __launch_bounds__(256, 3)
void edge_kernel(const float* __restrict__ e,
                 const int* __restrict__ ei32,
                 const float* __restrict__ We,
                 float* __restrict__ out)
{
    extern __shared__ __align__(16) float smf[];
    float* Wsh   = smf + SMF_W;    // [64][132]
    float* Ebase = smf + SMF_E;    // [2][32][68]

    const int tid  = threadIdx.x;
    const int lane = tid & 31;   // out-quad: lane*4 .. +3
    const int wy   = tid >> 5;   // edge group: wy*8 .. wy*8+7
    const int bid  = blockIdx.x;
    const int is64 = g_idx_is64;

    // One-time W fill: We[o][kq*4..] -> Wsh[kq*4+j][o], 2048 float4s.
#pragma unroll
    for (int it = 0; it < 8; ++it) {
        int idx = it * 256 + tid;       // 0..2047
        int o   = idx >> 4;             // 0..127
        int kq  = idx & 15;             // 0..15
        float4 w = reinterpret_cast<const float4*>(We)[idx];
        Wsh[(kq * 4 + 0) * 132 + o] = w.x;
        Wsh[(kq * 4 + 1) * 132 + o] = w.y;
        Wsh[(kq * 4 + 2) * 132 + o] = w.z;
        Wsh[(kq * 4 + 3) * 132 + o] = w.w;
    }

    // Stage fill: 64 edges x 32 k = 512 float4 -> 2 per thread.
    const int le0 = tid >> 3,         kq0 = tid & 7;          // idx = tid
    const int le1 = (256 + tid) >> 3, kq1 = (256 + tid) & 7;  // idx = tid+256

    const int ntiles = (NTILES_TOT - bid + EGRID - 1) / EGRID;   // 28 or 29
    const int NS     = 2 * ntiles;

    // Prologue: stage 0 (k 0..31) of tile bid into buffer 0.
    float4 pf0 = *reinterpret_cast<const float4*>(
        e + (size_t)(bid * ETILE + le0) * EDGE_DIM + kq0 * 4);
    float4 pf1 = *reinterpret_cast<const float4*>(
        e + (size_t)(bid * ETILE + le1) * EDGE_DIM + kq1 * 4);
    Ebase[(kq0 * 4 + 0) * 68 + le0] = pf0.x;
    Ebase[(kq0 * 4 + 1) * 68 + le0] = pf0.y;
    Ebase[(kq0 * 4 + 2) * 68 + le0] = pf0.z;
    Ebase[(kq0 * 4 + 3) * 68 + le0] = pf0.w;
    Ebase[(kq1 * 4 + 0) * 68 + le1] = pf1.x;
    Ebase[(kq1 * 4 + 1) * 68 + le1] = pf1.y;
    Ebase[(kq1 * 4 + 2) * 68 + le1] = pf1.z;
    Ebase[(kq1 * 4 + 3) * 68 + le1] = pf1.w;
    __syncthreads();

    u64 acc[4][4];

#pragma unroll 1
    for (int gs = 0; gs < NS; ++gs) {
        const int cur = gs & 1;        // buffer == stage-in-tile
        const int it  = gs >> 1;
        const int s   = gs & 1;
        const float* Ecur = Ebase + cur * (32 * 68);

        // prefetch next stage (possibly next tile's stage 0, stride EGRID)
        if (gs + 1 < NS) {
            const int nit = (gs + 1) >> 1, nss = (gs + 1) & 1;
            const int nt  = bid + nit * EGRID;
            pf0 = *reinterpret_cast<const float4*>(
                e + (size_t)(nt * ETILE + le0) * EDGE_DIM + nss * 32 + kq0 * 4);
            pf1 = *reinterpret_cast<const float4*>(
                e + (size_t)(nt * ETILE + le1) * EDGE_DIM + nss * 32 + kq1 * 4);
        }

        if (s == 0) {
#pragma unroll
            for (int p = 0; p < 4; ++p)
#pragma unroll
                for (int j = 0; j < 4; ++j) acc[p][j] = 0ULL;
        }

        // ---- 32 k-steps: 1 W LDS.128 (distinct) + 2 E LDS.128 (broadcast)
        //      + 4 dup movs + 16 fma2 per k ----
#pragma unroll
        for (int k = 0; k < 32; ++k) {
            const int kk = s * 32 + k;
            float4 w = *reinterpret_cast<const float4*>(&Wsh[kk * 132 + lane * 4]);
            u64 w2[4];
            w2[0] = pack2(w.x, w.x); w2[1] = pack2(w.y, w.y);
            w2[2] = pack2(w.z, w.z); w2[3] = pack2(w.w, w.w);
            u64 ev[4];
            {
                ulonglong2 ea = *reinterpret_cast<const ulonglong2*>(&Ecur[k * 68 + wy * 8]);
                ulonglong2 eb = *reinterpret_cast<const ulonglong2*>(&Ecur[k * 68 + wy * 8 + 4]);
                ev[0] = ea.x; ev[1] = ea.y; ev[2] = eb.x; ev[3] = eb.y;
            }
#pragma unroll
            for (int p = 0; p < 4; ++p)
#pragma unroll
                for (int j = 0; j < 4; ++j)
                    fma2(acc[p][j], ev[p], w2[j]);
        }

        // ---- publish prefetched stage + barrier FIRST (epilogue deferred) ----
        if (gs + 1 < NS) {
            float* En = Ebase + (cur ^ 1) * (32 * 68);
            En[(kq0 * 4 + 0) * 68 + le0] = pf0.x;
            En[(kq0 * 4 + 1) * 68 + le0] = pf0.y;
            En[(kq0 * 4 + 2) * 68 + le0] = pf0.z;
            En[(kq0 * 4 + 3) * 68 + le0] = pf0.w;
            En[(kq1 * 4 + 0) * 68 + le1] = pf1.x;
            En[(kq1 * 4 + 1) * 68 + le1] = pf1.y;
            En[(kq1 * 4 + 2) * 68 + le1] = pf1.z;
            En[(kq1 * 4 + 3) * 68 + le1] = pf1.w;
            __syncthreads();
        }

        // ---- deferred epilogue, batched gathers (2 halves x 2 edge-pairs) ----
        if (s == 1) {
            const int t    = bid + it * EGRID;
            const int base = t * ETILE + wy * 8;     // warp's 8 edges
#pragma unroll
            for (int hf = 0; hf < 2; ++hf) {
                const int eb4 = base + hf * 4;       // 4 edges this half
                int si[4], ti[4];
                if (!is64) {
                    int4 a = *reinterpret_cast<const int4*>(ei32 + eb4);
                    int4 b = *reinterpret_cast<const int4*>(ei32 + (size_t)N_EDGES + eb4);
                    si[0] = clamp_idx(a.x); si[1] = clamp_idx(a.y);
                    si[2] = clamp_idx(a.z); si[3] = clamp_idx(a.w);
                    ti[0] = clamp_idx(b.x); ti[1] = clamp_idx(b.y);
                    ti[2] = clamp_idx(b.z); ti[3] = clamp_idx(b.w);
                } else {
#pragma unroll
                    for (int i = 0; i < 4; ++i) {
                        si[i] = fetch_idx(ei32, 1, (size_t)(eb4 + i));
                        ti[i] = fetch_idx(ei32, 1, (size_t)N_EDGES + eb4 + i);
                    }
                }

                // issue ALL 8 row gathers before any arithmetic (MLP 8)
                float4 G[8];
#pragma unroll
                for (int i = 0; i < 4; ++i) {
                    G[2 * i]     = *reinterpret_cast<const float4*>(
                        g_HU + (size_t)si[i] * OUT_DIM + lane * 4);
                    G[2 * i + 1] = *reinterpret_cast<const float4*>(
                        g_HW + (size_t)ti[i] * OUT_DIM + lane * 4);
                }

#pragma unroll
                for (int q = 0; q < 2; ++q) {         // pair p = hf*2 + q
                    const int p  = hf * 2 + q;
                    const int ea = base + 2 * p;
                    float2 v0 = unpack2(acc[p][0]), v1 = unpack2(acc[p][1]);
                    float2 v2 = unpack2(acc[p][2]), v3 = unpack2(acc[p][3]);

                    float4 A = G[4 * q + 0], B = G[4 * q + 1];
                    float4 C = G[4 * q + 2], D = G[4 * q + 3];

                    *reinterpret_cast<float4*>(out + (size_t)ea * OUT_DIM + lane * 4) =
                        make_float4(v0.x + A.x + B.x, v1.x + A.y + B.y,
                                    v2.x + A.z + B.z, v3.x + A.w + B.w);
                    *reinterpret_cast<float4*>(out + (size_t)(ea + 1) * OUT_DIM + lane * 4) =
                        make_float4(v0.y + C.x + D.x, v1.y + C.y + D.y,
                                    v2.y + C.z + D.z, v3.y + C.w + D.w);
                }
            }
        }
    }
}

extern "C" void kernel_launch(void* const* d_in, const int* in_sizes, int n_in,
                              void* d_out, int out_size)
{
    const float* h   = (const float*)d_in[0];       // [50000,128]
    const float* e   = (const float*)d_in[1];       // [800000,64]
    const int*   ei  = (const int*)d_in[2];         // [2,800000]
    const float* We  = (const float*)d_in[3];       // [128,64]
    const float* Whu = (const float*)d_in[4];       // [128,128]
    const float* Whw = (const float*)d_in[5];       // [128,128]
    float*       out = (float*)d_out;               // [800000,128]

    dim3 ngrid((N_NODES + 127) / 128, 2);
    node_proj_kernel<<<ngrid, 256>>>(h, Whu, Whw, ei);

    cudaFuncSetAttribute(edge_kernel,
                         cudaFuncAttributeMaxDynamicSharedMemorySize, SM_TOTAL_B);
    edge_kernel<<<EGRID, 256, SM_TOTAL_B>>>(e, ei, We, out);
}